// round 5
// baseline (speedup 1.0000x reference)
#include <cuda_runtime.h>
#include <math.h>

#define B 32
#define C 256
#define MIP 8
#define HID 256
#define OUTD 14
#define TPB 256
#define NCTA 296           // 2 CTAs/SM on 148+ SMs; co-residency guaranteed
#define HALF_TILES 4096    // 16 batches * 256 channels

// scratch (device globals; no allocation)
__device__ float g_y[B * C * 128];      // concat(row-means, col-means)
__device__ float g_y2[B * MIP * 128];   // squeeze + bn + hswish
__device__ float g_att[B * C * 128];    // precomputed sigmoid attentions
__device__ float g_p[B * C];            // pooled features
__device__ float g_h[B * HID];          // fc1+bn+relu
__device__ unsigned g_cnt;              // barrier arrival counter (self-resetting)
__device__ unsigned g_gen;              // barrier generation (replay-safe usage)

__device__ __forceinline__ void grid_barrier() {
    __syncthreads();
    if (threadIdx.x == 0) {
        volatile unsigned* vg = &g_gen;
        unsigned cur = *vg;
        __threadfence();
        unsigned arrived = atomicAdd(&g_cnt, 1u);
        if (arrived == NCTA - 1u) {
            g_cnt = 0u;
            __threadfence();
            *vg = cur + 1u;
        } else {
            while (*vg == cur) { __nanosleep(32); }
            __threadfence();
        }
    }
    __syncthreads();
}

// ---------------------------------------------------------------------------
// Geometry — all float; transcendental-free except tanhf/softplus.
// ---------------------------------------------------------------------------
__device__ __forceinline__ float softplus_f(float x) {
    return fmaxf(x, 0.0f) + log1pf(expf(-fabsf(x)));
}

__device__ void geometry(int b, int e, const float* raws,
                         const float* __restrict__ Km,
                         const float* __restrict__ irisR,
                         float* __restrict__ out) {
    float t0 = raws[e * 7 + 0], t1 = raws[e * 7 + 1], t2 = raws[e * 7 + 2];
    float t3 = raws[e * 7 + 3], t4 = raws[e * 7 + 4], t5 = raws[e * 7 + 5];
    float t6 = raws[e * 7 + 6];

    float cx = t0, cy = t1;
    float ea = softplus_f(t2) + 1e-6f;
    float eb = softplus_f(t3) + 1e-6f;
    float nrm = sqrtf(t4 * t4 + t5 * t5);
    float cth = t4 / (nrm + 1e-8f);
    float sth = t5 / (nrm + 1e-8f);
    float delta = 0.3f * tanhf(t6);

    int be = b * 2 + e;
    out[be * 6 + 0] = cx;
    out[be * 6 + 1] = cy;
    out[be * 6 + 2] = ea;
    out[be * 6 + 3] = eb;
    out[be * 6 + 4] = cth;
    out[be * 6 + 5] = sth;
    out[384 + be] = delta;

    float ct, st;
    if (nrm > 0.f) { ct = t4 / nrm; st = t5 / nrm; }
    else           { ct = 1.f;      st = 0.f; }

    float ia2 = 1.0f / (ea * ea), ib2 = 1.0f / (eb * eb);
    float A11 = ct * ct * ia2 + st * st * ib2;
    float A22 = st * st * ia2 + ct * ct * ib2;
    float A12 = ct * st * (ia2 - ib2);
    float axv = A11 * cx + A12 * cy;
    float ayv = A12 * cx + A22 * cy;
    float cAc = A11 * cx * cx + 2.0f * A12 * cx * cy + A22 * cy * cy;

    float M[3][3] = {{A11, A12, -axv}, {A12, A22, -ayv}, {-axv, -ayv, cAc - 1.0f}};
    float Kd[3][3];
#pragma unroll
    for (int j = 0; j < 3; j++)
#pragma unroll
        for (int i = 0; i < 3; i++) Kd[j][i] = Km[b * 9 + j * 3 + i];

    float Cn[3][3];
#pragma unroll
    for (int i = 0; i < 3; i++)
#pragma unroll
        for (int l = 0; l < 3; l++) {
            float s = 0.0f;
#pragma unroll
            for (int j = 0; j < 3; j++) {
                float r = 0.0f;
#pragma unroll
                for (int k = 0; k < 3; k++) r += M[j][k] * Kd[k][l];
                s += Kd[j][i] * r;
            }
            Cn[i][l] = s;
        }

    float a00 = Cn[0][0], a01 = Cn[0][1], a10 = Cn[1][0], a11 = Cn[1][1];
    float u0 = Cn[0][2], u1 = Cn[1][2];
    float det = a00 * a11 - a01 * a10;
    float mu0 = (-u0 * a11 + a01 * u1) / det;
    float mu1 = (a10 * u0 - a00 * u1) / det;

    // slaev2 (LAPACK 2x2 symmetric eigh; lower triangle a00, a10, a11)
    float a = a00, bb = a10, cc = a11;
    float sm = a + cc, df = a - cc, adf = fabsf(df), tb = bb + bb, ab = fabsf(tb);
    float rt;
    if (adf > ab) { float q = ab / adf; rt = adf * sqrtf(1.0f + q * q); }
    else if (adf < ab) { float q = adf / ab; rt = ab * sqrtf(1.0f + q * q); }
    else rt = ab * sqrtf(2.0f);
    float rt1, rt2; int sgn1;
    if (sm < 0.0f) { rt1 = 0.5f * (sm - rt); sgn1 = -1; rt2 = (a / rt1) * cc - (bb / rt1) * bb; }
    else if (sm > 0.0f) { rt1 = 0.5f * (sm + rt); sgn1 = 1; rt2 = (a / rt1) * cc - (bb / rt1) * bb; }
    else { rt1 = 0.5f * rt; rt2 = -0.5f * rt; sgn1 = 1; }
    float cs; int sgn2;
    if (df >= 0.0f) { cs = df + rt; sgn2 = 1; } else { cs = df - rt; sgn2 = -1; }
    float acs = fabsf(cs), cs1, sn1;
    if (acs > ab) { float ctn = -tb / cs; sn1 = 1.0f / sqrtf(1.0f + ctn * ctn); cs1 = ctn * sn1; }
    else {
        if (ab == 0.0f) { cs1 = 1.0f; sn1 = 0.0f; }
        else { float tn = -cs / tb; cs1 = 1.0f / sqrtf(1.0f + tn * tn); sn1 = tn * cs1; }
    }
    if (sgn1 == sgn2) { float tt = cs1; cs1 = -sn1; sn1 = tt; }
    float lam0, lam1, v0, v1;
    if (rt1 <= rt2) { lam0 = rt1; lam1 = rt2; v0 = cs1; v1 = sn1; }
    else            { lam0 = rt2; lam1 = rt1; v0 = -sn1; v1 = cs1; }

    float a_n = 1.0f / sqrtf(fmaxf(lam0, 1e-12f));
    float b_n = 1.0f / sqrtf(fmaxf(lam1, 1e-12f));
    a_n = fmaxf(a_n, 1e-6f);
    float R = irisR[b];
    float z = fminf(fmaxf(R / a_n, 0.5f), 1000.0f);

    float rn = sqrtf(mu0 * mu0 + mu1 * mu1 + 1.0f) + 1e-8f;
    float icx = mu0 / rn * z, icy = mu1 / rn * z, icz = (1.0f / rn) * z;

    float ctl = fminf(fmaxf(b_n / a_n, 0.0f), 1.0f);
    float stl = sqrtf(fmaxf(1.0f - ctl * ctl, 0.0f));
    float hyp = sqrtf(v0 * v0 + v1 * v1);
    float kx = v0 / hyp, ky = v1 / hyp;
    float nx = ky * stl, ny = -kx * stl, nz = ctl;
    float nn = sqrtf(nx * nx + ny * ny + nz * nz) + 1e-8f;
    nx /= nn; ny /= nn; nz /= nn;

    float px = icx + delta * nx, py = icy + delta * ny, pz = icz + delta * nz;

    out[448 + be * 3 + 0] = icx;
    out[448 + be * 3 + 1] = icy;
    out[448 + be * 3 + 2] = icz;
    out[640 + be * 3 + 0] = nx;
    out[640 + be * 3 + 1] = ny;
    out[640 + be * 3 + 2] = nz;
    out[832 + be * 3 + 0] = px;
    out[832 + be * 3 + 1] = py;
    out[832 + be * 3 + 2] = pz;
    out[1024 + be] = z;
}

// ---------------------------------------------------------------------------
// The fused persistent kernel
// ---------------------------------------------------------------------------
__global__ void __launch_bounds__(TPB, 2)
fused(const float* __restrict__ x,
      const float* __restrict__ Km, const float* __restrict__ irisR,
      const float* __restrict__ w1,
      const float* __restrict__ bng, const float* __restrict__ bnb,
      const float* __restrict__ bnm, const float* __restrict__ bnv,
      const float* __restrict__ wh, const float* __restrict__ ww,
      const float* __restrict__ fc1w, const float* __restrict__ fc1b,
      const float* __restrict__ bn1g, const float* __restrict__ bn1b,
      const float* __restrict__ bn1m, const float* __restrict__ bn1v,
      const float* __restrict__ fow, const float* __restrict__ fob,
      float* __restrict__ out) {
    int cta = blockIdx.x;
    int tid = threadIdx.x;

    __shared__ union SMem {
        float tile[64 * 65];
        float w1s[MIP * C];
        struct { float att[128]; float red[8]; } c;
        struct { float ps[C]; } d;
        struct { float hs[HID]; float raws[OUTD]; } e;
    } sm;

    for (int half = 0; half < 2; half++) {
        int base = half * HALF_TILES;

        // ---- Phase A: row/col means (streams x half into L2) ------------
        {
            float4 r[4];
            int t = cta;
            if (t < HALF_TILES) {
                const float4* xt = (const float4*)(x + (size_t)(base + t) * 4096);
#pragma unroll
                for (int k = 0; k < 4; k++) r[k] = xt[tid + k * 256];
            }
            while (t < HALF_TILES) {
#pragma unroll
                for (int k = 0; k < 4; k++) {
                    int i = tid + k * 256;
                    int rr = i >> 4, cc = (i & 15) << 2;
                    float* d = &sm.tile[rr * 65 + cc];
                    d[0] = r[k].x; d[1] = r[k].y; d[2] = r[k].z; d[3] = r[k].w;
                }
                int tn = t + NCTA;
                __syncthreads();
                if (tn < HALF_TILES) {   // prefetch next tile during reduce
                    const float4* xt = (const float4*)(x + (size_t)(base + tn) * 4096);
#pragma unroll
                    for (int k = 0; k < 4; k++) r[k] = xt[tid + k * 256];
                }
                int bc = base + t;
                if (tid < 64) {
                    float s = 0.f;
#pragma unroll
                    for (int j = 0; j < 64; j++) s += sm.tile[tid * 65 + j];
                    g_y[(size_t)bc * 128 + tid] = s * (1.0f / 64.0f);
                } else if (tid < 128) {
                    int w = tid - 64;
                    float s = 0.f;
#pragma unroll
                    for (int h = 0; h < 64; h++) s += sm.tile[h * 65 + w];
                    g_y[(size_t)bc * 128 + 64 + w] = s * (1.0f / 64.0f);
                }
                __syncthreads();
                t = tn;
            }
        }
        grid_barrier();

        // ---- Phase B1: squeeze MLP for this half's 16 batches -----------
        if (cta < 64) {
            int u = cta;
            int b = half * 16 + (u >> 2);
            int lbase = (u & 3) * 32;
            for (int i = tid; i < MIP * C; i += TPB) sm.w1s[i] = w1[i];
            __syncthreads();
            int m = tid >> 5, li = tid & 31, l = lbase + li;
            const float* yb = g_y + (size_t)b * C * 128;
            float acc = 0.f;
#pragma unroll 8
            for (int c = 0; c < C; c++) acc += sm.w1s[m * C + c] * yb[c * 128 + l];
            float sc = bng[m] * rsqrtf(bnv[m] + 1e-5f);
            float v = (acc - bnm[m]) * sc + bnb[m];
            g_y2[b * (MIP * 128) + m * 128 + l] =
                v * fminf(fmaxf(v + 3.0f, 0.0f), 6.0f) * (1.0f / 6.0f);
        }
        grid_barrier();

        // ---- Phase B2: precompute all sigmoid attentions ----------------
        for (int u = cta; u < HALF_TILES; u += NCTA) {
            int bc = base + u;
            int b = bc >> 8, c = bc & 255;
            if (tid < 128) {
                const float* wm = (tid < 64) ? (wh + c * MIP) : (ww + c * MIP);
                const float* y2b = g_y2 + b * (MIP * 128);
                float s = 0.f;
#pragma unroll
                for (int m = 0; m < MIP; m++) s += wm[m] * y2b[m * 128 + tid];
                g_att[(size_t)bc * 128 + tid] = 1.0f / (1.0f + __expf(-s));
            }
        }
        grid_barrier();

        // ---- Phase C: weighted pool; x half re-read from hot L2 ---------
        {
            float4 r[4];
            int t = cta;
            if (t < HALF_TILES) {
                const float4* xt = (const float4*)(x + (size_t)(base + t) * 4096);
#pragma unroll
                for (int k = 0; k < 4; k++) r[k] = xt[tid + k * 256];
            }
            while (t < HALF_TILES) {
                int bc = base + t;
                if (tid < 128) sm.c.att[tid] = g_att[(size_t)bc * 128 + tid];
                __syncthreads();
                float acc = 0.f;
#pragma unroll
                for (int k = 0; k < 4; k++) {
                    int i = tid + k * 256;
                    int rr = i >> 4, c4 = (i & 15) << 2;
                    float ah = sm.c.att[rr];
                    acc += ah * (r[k].x * sm.c.att[64 + c4] +
                                 r[k].y * sm.c.att[64 + c4 + 1] +
                                 r[k].z * sm.c.att[64 + c4 + 2] +
                                 r[k].w * sm.c.att[64 + c4 + 3]);
                }
                int tn = t + NCTA;
                if (tn < HALF_TILES) {   // prefetch next tile during reduce
                    const float4* xt = (const float4*)(x + (size_t)(base + tn) * 4096);
#pragma unroll
                    for (int k = 0; k < 4; k++) r[k] = xt[tid + k * 256];
                }
                for (int off = 16; off; off >>= 1)
                    acc += __shfl_down_sync(0xffffffffu, acc, off);
                if ((tid & 31) == 0) sm.c.red[tid >> 5] = acc;
                __syncthreads();
                if (tid == 0) {
                    float s = 0.f;
#pragma unroll
                    for (int i = 0; i < 8; i++) s += sm.c.red[i];
                    g_p[bc] = s * (1.0f / 4096.0f);
                }
                __syncthreads();
                t = tn;
            }
        }
        grid_barrier();
    }

    // ---- Phase D: fc1 + bn + relu (256 units) ---------------------------
    if (cta < 256) {
        int b = cta >> 3, g = cta & 7;
        sm.d.ps[tid] = g_p[b * C + tid];
        __syncthreads();
        int warp = tid >> 5, lane = tid & 31;
        int j0 = g * 32 + warp * 4;
        float a0 = 0.f, a1 = 0.f, a2 = 0.f, a3 = 0.f;
#pragma unroll
        for (int k = 0; k < 8; k++) {
            int cc = lane + 32 * k;
            float pv = sm.d.ps[cc];
            a0 += pv * fc1w[(j0 + 0) * C + cc];
            a1 += pv * fc1w[(j0 + 1) * C + cc];
            a2 += pv * fc1w[(j0 + 2) * C + cc];
            a3 += pv * fc1w[(j0 + 3) * C + cc];
        }
        float accs[4] = {a0, a1, a2, a3};
#pragma unroll
        for (int q = 0; q < 4; q++) {
            float v = accs[q];
            for (int off = 16; off; off >>= 1)
                v += __shfl_down_sync(0xffffffffu, v, off);
            if (lane == 0) {
                int j = j0 + q;
                v += fc1b[j];
                float sc = bn1g[j] * rsqrtf(bn1v[j] + 1e-5f);
                v = (v - bn1m[j]) * sc + bn1b[j];
                g_h[b * HID + j] = fmaxf(v, 0.0f);
            }
        }
    }
    grid_barrier();

    // ---- Phase E: fc_out + geometry (32 units) --------------------------
    if (cta < 32) {
        int b = cta;
        sm.e.hs[tid] = g_h[b * HID + tid];
        __syncthreads();
        int warp = tid >> 5, lane = tid & 31;
        for (int o = warp; o < OUTD; o += 8) {
            float part = 0.f;
#pragma unroll
            for (int k = 0; k < 8; k++) {
                int c = lane + 32 * k;
                part += sm.e.hs[c] * fow[o * HID + c];
            }
            for (int off = 16; off; off >>= 1)
                part += __shfl_down_sync(0xffffffffu, part, off);
            if (lane == 0) sm.e.raws[o] = part + fob[o];
        }
        __syncthreads();
        if (tid < 2) geometry(b, tid, sm.e.raws, Km, irisR, out);
    }
}

// ---------------------------------------------------------------------------
extern "C" void kernel_launch(void* const* d_in, const int* in_sizes, int n_in,
                              void* d_out, int out_size) {
    const float* x     = (const float*)d_in[0];
    const float* Km    = (const float*)d_in[1];
    const float* irisR = (const float*)d_in[2];
    const float* ca_w1 = (const float*)d_in[3];
    const float* ca_bn_g = (const float*)d_in[4];
    const float* ca_bn_b = (const float*)d_in[5];
    const float* ca_bn_m = (const float*)d_in[6];
    const float* ca_bn_v = (const float*)d_in[7];
    const float* ca_wh = (const float*)d_in[8];
    const float* ca_ww = (const float*)d_in[9];
    const float* fc1_w = (const float*)d_in[10];
    const float* fc1_b = (const float*)d_in[11];
    const float* bn1_g = (const float*)d_in[12];
    const float* bn1_b = (const float*)d_in[13];
    const float* bn1_m = (const float*)d_in[14];
    const float* bn1_v = (const float*)d_in[15];
    const float* fc_out_w = (const float*)d_in[16];
    const float* fc_out_b = (const float*)d_in[17];
    float* out = (float*)d_out;

    fused<<<NCTA, TPB>>>(x, Km, irisR, ca_w1, ca_bn_g, ca_bn_b, ca_bn_m, ca_bn_v,
                         ca_wh, ca_ww, fc1_w, fc1_b, bn1_g, bn1_b, bn1_m, bn1_v,
                         fc_out_w, fc_out_b, out);
}